// round 16
// baseline (speedup 1.0000x reference)
#include <cuda_runtime.h>
#include <cuda_bf16.h>
#include <cstdint>
#include <cstddef>

// ============================================================================
// QuantumCoherentLayer — collapsed algebra (base sm_103: mma.sync + cp.async)
//
//   w[j]  = sum_i softmax_row_i(cos(phase * J_sym))[j]
//   alpha = clip(exp(-t/51), 0, 1)
//   W_eff = sum_j w[j] * W_paths[j];  M = W_input @ W_eff
//   out   = (a^2/64)*sum_j w[j]*coherent[:,j,:] + (a(1-a)/64)*(x @ M)
//
// R14: collapse launch graph 5 -> 3 nodes. Scalars are recomputed per-block
// (cheap: 8x8 cos + softmax) instead of a dedicated kernel; conv+wet merged
// into k_prep so the two independent streams overlap. GEMM2 computes w/c1 in
// static smem while its prologue cp.async stages are in flight. GEMM math
// unchanged (bf16 m16n8k16; GEMM2 fuses coh into mainloop accumulators via
// x pre-scaled by (1-a)/a; out = c1*acc).
// ============================================================================

#define PI_F 3.14159265358979323846f

static constexpr int H = 1024;
static constexpr int B = 2048;
static constexpr int STAGES = 4;

// ---------------- device scratch (no cudaMalloc allowed) ---------------------
__device__ uint16_t g_WeTb[H * H];     // WeT[n][h] = W_eff[h][n]  (bf16)
__device__ uint16_t g_Wib[H * H];      // W_input   (bf16, row-major [d][h])
__device__ uint16_t g_Mtb[H * H];      // Mt[n][d]  = M[d][n]      (bf16)
__device__ uint16_t g_xb[B * H];       // x * (1-a)/a              (bf16)

// ---------------- asm helpers ------------------------------------------------
__device__ __forceinline__ uint32_t smem_u32(const void* p) {
    uint32_t a;
    asm("{ .reg .u64 t; cvta.to.shared.u64 t, %1; cvt.u32.u64 %0, t; }" : "=r"(a) : "l"(p));
    return a;
}
__device__ __forceinline__ void cp16(uint32_t s, const void* g) {
    asm volatile("cp.async.cg.shared.global [%0], [%1], 16;" :: "r"(s), "l"(g) : "memory");
}
#define CP_COMMIT() asm volatile("cp.async.commit_group;" ::: "memory")
#define CP_WAIT(n)  asm volatile("cp.async.wait_group %0;" :: "n"(n) : "memory")

// volatile: ptxas may not reorder/coalesce these -> forced back-to-back LDGs
__device__ __forceinline__ float4 ldg_v4_nc(const float* p) {
    float4 v;
    asm volatile("ld.global.nc.v4.f32 {%0,%1,%2,%3}, [%4];"
                 : "=f"(v.x), "=f"(v.y), "=f"(v.z), "=f"(v.w) : "l"(p));
    return v;
}

__device__ __forceinline__ void mma_bf16_16(float* d, const uint32_t* a, const uint32_t* b) {
    asm volatile(
        "mma.sync.aligned.m16n8k16.row.col.f32.bf16.bf16.f32 "
        "{%0,%1,%2,%3}, {%4,%5,%6,%7}, {%8,%9}, {%0,%1,%2,%3};"
        : "+f"(d[0]), "+f"(d[1]), "+f"(d[2]), "+f"(d[3])
        : "r"(a[0]), "r"(a[1]), "r"(a[2]), "r"(a[3]), "r"(b[0]), "r"(b[1]));
}

// ---------------- per-block scalar computation --------------------------------
// Computes w[0..7] into sw[0..7] and alpha-derived constant into sw[8]
// (mode 0: c1 = a^2/64;  mode 1: (1-a)/a).  Uses tid<64. Caller syncs after.
__device__ __forceinline__ void block_scalars(const float* __restrict__ J,
                                              float tv, int tid,
                                              float (*S)[8], float (*R)[8],
                                              float* sw, int mode) {
    float phase = 2.0f * PI_F * 20.0f * tv / 1000.0f;
    if (tid < 64) {
        int i = tid >> 3, j = tid & 7;
        S[i][j] = cosf(phase * 0.5f * (J[i * 8 + j] + J[j * 8 + i]));
    }
    __syncthreads();
    if (tid < 8) {
        int i = tid;
        float mx = -1e30f;
        #pragma unroll
        for (int j = 0; j < 8; j++) mx = fmaxf(mx, S[i][j]);
        float e[8], s = 0.0f;
        #pragma unroll
        for (int j = 0; j < 8; j++) { e[j] = expf(S[i][j] - mx); s += e[j]; }
        float inv = 1.0f / s;
        #pragma unroll
        for (int j = 0; j < 8; j++) R[i][j] = e[j] * inv;
    }
    __syncthreads();
    if (tid < 8) {
        int j = tid;
        float wv = 0.0f;
        #pragma unroll
        for (int i = 0; i < 8; i++) wv += R[i][j];
        sw[j] = wv;
    }
    if (tid == 0) {
        float a = expf(-tv / 51.0f);
        a = fminf(fmaxf(a, 0.0f), 1.0f);
        sw[8] = (mode == 0) ? (a * a / 64.0f) : ((1.0f - a) / a);
    }
}

// ============================================================================
// k_prep: merged  WeTb (weighted transpose, needs w)  +  xb (needs (1-a)/a)
//         +  Wib (plain bf16 convert)
//   blocks [0, NWET)            -> wet part (32h x 64n tiles)
//   blocks [NWET, NWET+NXB)     -> x part
//   blocks [NWET+NXB, end)      -> Wi part
// ============================================================================
static constexpr int NWET = 512;                     // 32 x 16 tiles
static constexpr int NXB  = (B * H / 4) / 256;       // 2048 blocks
static constexpr int NWB  = (H * H / 4) / 256;       // 1024 blocks

__global__ void __launch_bounds__(256) k_prep(const float* __restrict__ x,
                                              const float* __restrict__ Wi,
                                              const float* __restrict__ Wp,
                                              const float* __restrict__ J,
                                              const float* __restrict__ t) {
    int bid = blockIdx.x;
    int tid = threadIdx.x;

    if (bid < NWET) {
        // ---- weighted transpose tile ----
        __shared__ float S[8][8], R[8][8], sw[9];
        __shared__ float tile[32][65];
        block_scalars(J, t[0], tid, S, R, sw, 0);
        __syncthreads();
        float w[8];
        #pragma unroll
        for (int j = 0; j < 8; j++) w[j] = sw[j];

        int h0 = (bid & 31) * 32, n0 = (bid >> 5) * 64;

        int i0 = tid, i1 = 256 + tid;
        int r0 = i0 >> 4, c0 = i0 & 15;
        int r1 = i1 >> 4, c1 = i1 & 15;
        const float* p0 = Wp + (size_t)(h0 + r0) * H + n0 + c0 * 4;
        const float* p1 = Wp + (size_t)(h0 + r1) * H + n0 + c1 * 4;

        float4 v[2][8];
        #pragma unroll
        for (int j = 0; j < 8; j++) v[0][j] = ldg_v4_nc(p0 + (size_t)j * H * H);
        #pragma unroll
        for (int j = 0; j < 8; j++) v[1][j] = ldg_v4_nc(p1 + (size_t)j * H * H);

        #pragma unroll
        for (int it = 0; it < 2; it++) {
            float4 acc = make_float4(0.f, 0.f, 0.f, 0.f);
            #pragma unroll
            for (int j = 0; j < 8; j++) {
                acc.x += w[j] * v[it][j].x; acc.y += w[j] * v[it][j].y;
                acc.z += w[j] * v[it][j].z; acc.w += w[j] * v[it][j].w;
            }
            int r = it ? r1 : r0, c4 = it ? c1 : c0;
            tile[r][c4 * 4 + 0] = acc.x;
            tile[r][c4 * 4 + 1] = acc.y;
            tile[r][c4 * 4 + 2] = acc.z;
            tile[r][c4 * 4 + 3] = acc.w;
        }
        __syncthreads();
        #pragma unroll
        for (int it = 0; it < 4; it++) {
            int i = it * 256 + tid;
            int n = i >> 4, hp = i & 15;
            __nv_bfloat162 pv = __float22bfloat162_rn(
                make_float2(tile[2 * hp][n], tile[2 * hp + 1][n]));
            *(uint32_t*)(g_WeTb + (size_t)(n0 + n) * H + h0 + 2 * hp) = *(uint32_t*)&pv;
        }
    } else if (bid < NWET + NXB) {
        // ---- x -> bf16 scaled by (1-a)/a (alpha computed thread-locally) ----
        float a = expf(-t[0] / 51.0f);
        a = fminf(fmaxf(a, 0.0f), 1.0f);
        float s = (1.0f - a) / a;
        int idx = (bid - NWET) * 256 + tid;
        float4 v = *(const float4*)(x + (size_t)idx * 4);
        __nv_bfloat162 lo = __float22bfloat162_rn(make_float2(v.x * s, v.y * s));
        __nv_bfloat162 hi = __float22bfloat162_rn(make_float2(v.z * s, v.w * s));
        uint2 pk;
        pk.x = *(uint32_t*)&lo;
        pk.y = *(uint32_t*)&hi;
        *(uint2*)(g_xb + (size_t)idx * 4) = pk;
    } else {
        // ---- Wi -> bf16 ----
        int idx = (bid - NWET - NXB) * 256 + tid;
        float4 v = *(const float4*)(Wi + (size_t)idx * 4);
        __nv_bfloat162 lo = __float22bfloat162_rn(make_float2(v.x, v.y));
        __nv_bfloat162 hi = __float22bfloat162_rn(make_float2(v.z, v.w));
        uint2 pk;
        pk.x = *(uint32_t*)&lo;
        pk.y = *(uint32_t*)&hi;
        *(uint2*)(g_Wib + (size_t)idx * 4) = pk;
    }
}

// ============================================================================
// GEMM1 (bf16): Mtb[n][d] = bf16( sum_h WeTb[n][h] * Wib[d][h] )
//   CTA 64x128, 8 warps of 32x32, m16n8k16, KTILE=64 bf16, 4-stage cp.async.
// ============================================================================
__global__ void __launch_bounds__(256, 1)
k_gemm1(const uint16_t* __restrict__ A, const uint16_t* __restrict__ Bm) {
    constexpr int BM = 64, BN = 128, T = 256;
    constexpr int NKC = 16;
    constexpr int ABYTES = BM * 128;
    constexpr int BBYTES = BN * 128;
    constexpr int STAGE_BYTES = ABYTES + BBYTES;

    extern __shared__ char smem[];
    uint32_t sbase = smem_u32(smem);

    int tid = threadIdx.x;
    int wid = tid >> 5, l = tid & 31;
    int wm = wid % 2, wn = wid / 2;
    int m0 = blockIdx.y * BM;
    int n0 = blockIdx.x * BN;
    int g = l >> 2, c = l & 3;
    int p4 = (g & 1) * 4;

    const uint16_t* gA = A + (size_t)m0 * H;
    const uint16_t* gB = Bm + (size_t)n0 * H;

    auto load_stage = [&](int kc, int stage) {
        uint32_t sA = sbase + stage * STAGE_BYTES;
        uint32_t sB = sA + ABYTES;
        const uint16_t* pA = gA + kc * 64;
        const uint16_t* pB = gB + kc * 64;
        #pragma unroll
        for (int i = tid; i < BM * 8; i += T) {
            int r = i >> 3, ch = i & 7;
            cp16(sA + r * 128 + ((ch ^ ((r & 1) * 4)) << 4), pA + (size_t)r * H + ch * 8);
        }
        #pragma unroll
        for (int i = tid; i < BN * 8; i += T) {
            int r = i >> 3, ch = i & 7;
            cp16(sB + r * 128 + ((ch ^ ((r & 1) * 4)) << 4), pB + (size_t)r * H + ch * 8);
        }
    };

    #pragma unroll
    for (int s = 0; s < STAGES - 1; s++) { load_stage(s, s); CP_COMMIT(); }

    float acc[2][4][4];
    #pragma unroll
    for (int mf = 0; mf < 2; mf++)
        #pragma unroll
        for (int f = 0; f < 4; f++)
            #pragma unroll
            for (int q = 0; q < 4; q++) acc[mf][f][q] = 0.0f;

    int rowA = wm * 32 + g;
    int rowB = wn * 32 + g;

    #pragma unroll 1
    for (int kc0 = 0; kc0 < NKC; kc0 += 4) {
        #pragma unroll
        for (int s4 = 0; s4 < 4; s4++) {
            int kc = kc0 + s4;
            CP_WAIT(STAGES - 2);
            __syncthreads();
            if (kc + STAGES - 1 < NKC) load_stage(kc + STAGES - 1, (kc + STAGES - 1) & 3);
            CP_COMMIT();

            const char* tA = smem + s4 * STAGE_BYTES;
            const char* tB = tA + ABYTES;

            #pragma unroll
            for (int hstep = 0; hstep < 2; hstep++) {
                int ch = (4 * hstep + c) ^ p4;
                uint4 av[4];
                #pragma unroll
                for (int rr = 0; rr < 4; rr++)
                    av[rr] = *(const uint4*)(tA + (rowA + rr * 8) * 128 + ch * 16);
                uint4 bv[4];
                #pragma unroll
                for (int f = 0; f < 4; f++)
                    bv[f] = *(const uint4*)(tB + (rowB + f * 8) * 128 + ch * 16);
                #pragma unroll
                for (int q = 0; q < 2; q++) {
                    #pragma unroll
                    for (int mf = 0; mf < 2; mf++) {
                        uint32_t a[4];
                        if (q == 0) {
                            a[0] = av[2 * mf].x; a[1] = av[2 * mf + 1].x;
                            a[2] = av[2 * mf].y; a[3] = av[2 * mf + 1].y;
                        } else {
                            a[0] = av[2 * mf].z; a[1] = av[2 * mf + 1].z;
                            a[2] = av[2 * mf].w; a[3] = av[2 * mf + 1].w;
                        }
                        #pragma unroll
                        for (int f = 0; f < 4; f++) {
                            uint32_t b[2];
                            if (q == 0) { b[0] = bv[f].x; b[1] = bv[f].y; }
                            else        { b[0] = bv[f].z; b[1] = bv[f].w; }
                            mma_bf16_16(acc[mf][f], a, b);
                        }
                    }
                }
            }
        }
    }

    #pragma unroll
    for (int mf = 0; mf < 2; mf++) {
        #pragma unroll
        for (int hh = 0; hh < 2; hh++) {
            int row = m0 + wm * 32 + mf * 16 + hh * 8 + g;
            #pragma unroll
            for (int f = 0; f < 4; f++) {
                int col = n0 + wn * 32 + f * 8 + 2 * c;
                __nv_bfloat162 pv = __float22bfloat162_rn(
                    make_float2(acc[mf][f][2 * hh], acc[mf][f][2 * hh + 1]));
                *(uint32_t*)(g_Mtb + (size_t)row * H + col) = *(uint32_t*)&pv;
            }
        }
    }
}

// ============================================================================
// GEMM2 (bf16 + fused coh): acc = xb@Mtb^T + sum_j w[j]*coh ; out = c1*acc
//   CTA 128x128, 16 warps of 32x32, m16n8k16, KTILE=64 bf16, 4-stage cp.async.
//   w/c1 computed per-block in static smem while prologue stages are in flight.
//   Per ktile kc: j=kc>>1, mf=kc&1 -> 8 __ldcs float2 of coh + 16 FFMA into acc.
// ============================================================================
__global__ void __launch_bounds__(512, 1)
k_gemm2(const uint16_t* __restrict__ A, const uint16_t* __restrict__ Bm,
        float* __restrict__ out, const float* __restrict__ coh,
        const float* __restrict__ J, const float* __restrict__ t) {
    constexpr int BM = 128, BN = 128, T = 512;
    constexpr int NKC = 16;
    constexpr int ABYTES = BM * 128;
    constexpr int BBYTES = BN * 128;
    constexpr int STAGE_BYTES = ABYTES + BBYTES;

    extern __shared__ char smem[];
    __shared__ float S[8][8], R[8][8], sw[9];
    uint32_t sbase = smem_u32(smem);

    int tid = threadIdx.x;
    int wid = tid >> 5, l = tid & 31;
    int wm = wid % 4, wn = wid / 4;
    int m0 = blockIdx.y * BM;
    int n0 = blockIdx.x * BN;
    int g = l >> 2, c = l & 3;
    int p4 = (g & 1) * 4;

    const uint16_t* gA = A + (size_t)m0 * H;
    const uint16_t* gB = Bm + (size_t)n0 * H;

    const float* cohbase = coh + n0 + wn * 32 + 2 * c;

    auto load_stage = [&](int kc, int stage) {
        uint32_t sA = sbase + stage * STAGE_BYTES;
        uint32_t sB = sA + ABYTES;
        const uint16_t* pA = gA + kc * 64;
        const uint16_t* pB = gB + kc * 64;
        #pragma unroll
        for (int i = tid; i < BM * 8; i += T) {
            int r = i >> 3, ch = i & 7;
            cp16(sA + r * 128 + ((ch ^ ((r & 1) * 4)) << 4), pA + (size_t)r * H + ch * 8);
        }
        #pragma unroll
        for (int i = tid; i < BN * 8; i += T) {
            int r = i >> 3, ch = i & 7;
            cp16(sB + r * 128 + ((ch ^ ((r & 1) * 4)) << 4), pB + (size_t)r * H + ch * 8);
        }
    };

    #pragma unroll
    for (int s = 0; s < STAGES - 1; s++) { load_stage(s, s); CP_COMMIT(); }

    // scalars computed while the prologue cp.async stages are in flight
    block_scalars(J, t[0], tid, S, R, sw, 0);
    __syncthreads();
    float w[8];
    #pragma unroll
    for (int j = 0; j < 8; j++) w[j] = sw[j];

    float acc[2][4][4];
    #pragma unroll
    for (int mf = 0; mf < 2; mf++)
        #pragma unroll
        for (int f = 0; f < 4; f++)
            #pragma unroll
            for (int q = 0; q < 4; q++) acc[mf][f][q] = 0.0f;

    int rowA = wm * 32 + g;
    int rowB = wn * 32 + g;

    #pragma unroll 1
    for (int kc0 = 0; kc0 < NKC; kc0 += 4) {
        #pragma unroll
        for (int s4 = 0; s4 < 4; s4++) {
            int kc = kc0 + s4;
            CP_WAIT(STAGES - 2);
            __syncthreads();
            if (kc + STAGES - 1 < NKC) load_stage(kc + STAGES - 1, (kc + STAGES - 1) & 3);
            CP_COMMIT();

            // ---- coh loads for (j = kc>>1, mf = kc&1) ----
            int j = kc >> 1;
            int mfc = kc & 1;
            float2 ct[2][4];
            {
                #pragma unroll
                for (int hh = 0; hh < 2; hh++) {
                    int row = m0 + wm * 32 + mfc * 16 + hh * 8 + g;
                    const float* cp = cohbase + ((size_t)row * 8 + j) * H;
                    #pragma unroll
                    for (int f = 0; f < 4; f++)
                        ct[hh][f] = __ldcs((const float2*)(cp + f * 8));
                }
            }

            const char* tA = smem + s4 * STAGE_BYTES;
            const char* tB = tA + ABYTES;

            #pragma unroll
            for (int hstep = 0; hstep < 2; hstep++) {
                int ch = (4 * hstep + c) ^ p4;
                uint4 av[4];
                #pragma unroll
                for (int rr = 0; rr < 4; rr++)
                    av[rr] = *(const uint4*)(tA + (rowA + rr * 8) * 128 + ch * 16);
                uint4 bv[4];
                #pragma unroll
                for (int f = 0; f < 4; f++)
                    bv[f] = *(const uint4*)(tB + (rowB + f * 8) * 128 + ch * 16);
                #pragma unroll
                for (int q = 0; q < 2; q++) {
                    #pragma unroll
                    for (int mf = 0; mf < 2; mf++) {
                        uint32_t a[4];
                        if (q == 0) {
                            a[0] = av[2 * mf].x; a[1] = av[2 * mf + 1].x;
                            a[2] = av[2 * mf].y; a[3] = av[2 * mf + 1].y;
                        } else {
                            a[0] = av[2 * mf].z; a[1] = av[2 * mf + 1].z;
                            a[2] = av[2 * mf].w; a[3] = av[2 * mf + 1].w;
                        }
                        #pragma unroll
                        for (int f = 0; f < 4; f++) {
                            uint32_t b[2];
                            if (q == 0) { b[0] = bv[f].x; b[1] = bv[f].y; }
                            else        { b[0] = bv[f].z; b[1] = bv[f].w; }
                            mma_bf16_16(acc[mf][f], a, b);
                        }
                    }
                }
            }

            // ---- apply coh FMAs into acc ----
            float wj = w[j];
            #pragma unroll
            for (int hh = 0; hh < 2; hh++) {
                #pragma unroll
                for (int f = 0; f < 4; f++) {
                    acc[mfc][f][2 * hh]     += wj * ct[hh][f].x;
                    acc[mfc][f][2 * hh + 1] += wj * ct[hh][f].y;
                }
            }
        }
    }

    // ----------------- epilogue: out = c1 * acc -----------------
    float c1 = sw[8];
    #pragma unroll
    for (int mf = 0; mf < 2; mf++) {
        #pragma unroll
        for (int hh = 0; hh < 2; hh++) {
            int row = m0 + wm * 32 + mf * 16 + hh * 8 + g;
            #pragma unroll
            for (int f = 0; f < 4; f++) {
                int col = n0 + wn * 32 + f * 8 + 2 * c;
                *(float2*)(out + (size_t)row * H + col) =
                    make_float2(c1 * acc[mf][f][2 * hh], c1 * acc[mf][f][2 * hh + 1]);
            }
        }
    }
}

// ============================================================================
// Host side — 3 graph nodes: k_prep -> k_gemm1 -> k_gemm2
// ============================================================================
extern "C" void kernel_launch(void* const* d_in, const int* in_sizes, int n_in,
                              void* d_out, int out_size) {
    const float* x   = (const float*)d_in[0];   // [2048, 1024]
    const float* Wi  = (const float*)d_in[1];   // [1024, 1024]
    const float* Wp  = (const float*)d_in[2];   // [8, 1024, 1024]
    const float* J   = (const float*)d_in[3];   // [8, 8]
    const float* coh = (const float*)d_in[4];   // [2048, 8, 1024]
    const float* t   = (const float*)d_in[5];   // [1]
    float* out = (float*)d_out;                 // [2048, 1024]
    (void)in_sizes; (void)n_in; (void)out_size;

    void* wetb_ptr = nullptr;
    void* wib_ptr = nullptr;
    void* mtb_ptr = nullptr;
    void* xb_ptr = nullptr;
    cudaGetSymbolAddress(&wetb_ptr, g_WeTb);
    cudaGetSymbolAddress(&wib_ptr, g_Wib);
    cudaGetSymbolAddress(&mtb_ptr, g_Mtb);
    cudaGetSymbolAddress(&xb_ptr, g_xb);

    constexpr int SMEM1 = STAGES * (64 * 128 + 128 * 128);    // 96 KB
    constexpr int SMEM2 = STAGES * (128 * 128 + 128 * 128);   // 128 KB
    cudaFuncSetAttribute((const void*)k_gemm1,
                         cudaFuncAttributeMaxDynamicSharedMemorySize, SMEM1);
    cudaFuncSetAttribute((const void*)k_gemm2,
                         cudaFuncAttributeMaxDynamicSharedMemorySize, SMEM2);

    // node 1: WeTb + xb + Wib (conv streams overlap the wet stream)
    k_prep<<<NWET + NXB + NWB, 256>>>(x, Wi, Wp, J, t);
    // node 2: Mtb[n][d] = bf16( sum_h WeTb[n][h] * Wib[d][h] )
    k_gemm1<<<dim3(8, 16), 256, SMEM1>>>(
        (const uint16_t*)wetb_ptr, (const uint16_t*)wib_ptr);
    // node 3: acc = xb@Mtb^T + sum_j w[j]*coh ; out = c1*acc
    k_gemm2<<<dim3(8, 16), 512, SMEM2>>>(
        (const uint16_t*)xb_ptr, (const uint16_t*)mtb_ptr, out, coh, J, t);
}